// round 1
// baseline (speedup 1.0000x reference)
#include <cuda_runtime.h>
#include <math.h>

// EntmaxBisect, alpha=1.5, d=4096, 50 bisection iters, p = 1/(d-1) (faithful).
//
// Analytic collapse: with p = 1/4095, every nonzero Z term u^p lies in
// [0.975, 1.0001] for any positive fp32 u. Hence the reference fp32 mask
// (sum(Z) - 1 >= 0) is exactly:
//     count(Xs > t) >= 2               <=>  t < s2 (second-largest of Xs)
//  || count == 1 && (m - t)^p rounds >= 1.0f   <=>  (m - t) >= U_TH
// so the bisection only needs per-row (max, second-max). We replicate the
// fp32 t_min/diff/t trajectory exactly; the final Z is nonzero for only
// ~2 elements/row, computed under a real branch.

#define NTHREADS 256
#define DIM_D 4096
#define VPT 16           // values per thread = 4 x float4
#define NWARPS (NTHREADS / 32)

__global__ __launch_bounds__(NTHREADS)
void entmax_bisect_kernel(const float* __restrict__ X, float* __restrict__ Y) {
    const int tid = threadIdx.x;
    const size_t row_off = (size_t)blockIdx.x * DIM_D;
    const float4* __restrict__ x4 = reinterpret_cast<const float4*>(X + row_off);
    float4* __restrict__ y4 = reinterpret_cast<float4*>(Y + row_off);

    // ---- load row, Xs = (alpha-1)*X = 0.5*X (exact in fp32) ----
    float xs[VPT];
#pragma unroll
    for (int j = 0; j < 4; j++) {
        float4 v = x4[tid + j * NTHREADS];
        xs[4 * j + 0] = 0.5f * v.x;
        xs[4 * j + 1] = 0.5f * v.y;
        xs[4 * j + 2] = 0.5f * v.z;
        xs[4 * j + 3] = 0.5f * v.w;
    }

    // ---- per-thread top-2 (duplicates of the max count as second-max) ----
    float hi = -INFINITY, lo = -INFINITY;
#pragma unroll
    for (int i = 0; i < VPT; i++) {
        float v = xs[i];
        if (v >= hi) { lo = hi; hi = v; }
        else if (v > lo) { lo = v; }
    }
    // warp top-2 (symmetric butterfly combine)
#pragma unroll
    for (int off = 16; off > 0; off >>= 1) {
        float h2 = __shfl_xor_sync(0xFFFFFFFFu, hi, off);
        float l2 = __shfl_xor_sync(0xFFFFFFFFu, lo, off);
        if (h2 >= hi) { lo = fmaxf(hi, l2); hi = h2; }
        else          { lo = fmaxf(lo, h2); }
    }
    __shared__ float sh_hi[NWARPS];
    __shared__ float sh_lo[NWARPS];
    __shared__ float sh_sum[NWARPS];
    const int lane = tid & 31, wid = tid >> 5;
    if (lane == 0) { sh_hi[wid] = hi; sh_lo[wid] = lo; }
    __syncthreads();
    // every thread folds the 8 warp results (cheap, gives uniform m/s2)
    float m = -INFINITY, s2 = -INFINITY;
#pragma unroll
    for (int w = 0; w < NWARPS; w++) {
        float h2 = sh_hi[w];
        if (h2 >= m) { s2 = fmaxf(m, sh_lo[w]); m = h2; }
        else         { s2 = fmaxf(s2, h2); }
    }

    // ---- scalar bisection, bit-faithful fp32 trajectory ----
    // t_max = m - d^(1-alpha) = m - 1/64 exactly.
    float t_min = m - 1.0f;
    float t_max = m - 0.015625f;
    float diff  = t_max - t_min;
    // (m-t)^(1/4095) rounds to >= 1.0f iff (m-t) >= ~0.99987796 (see header).
    const float U_TH = 0.99987796f;
    float t = t_min;
#pragma unroll 1
    for (int it = 0; it < 50; it++) {
        diff = diff * 0.5f;
        t = t_min + diff;
        bool mask = (t < s2) || ((m - t) >= U_TH);
        if (mask) t_min = t;
    }
    // Z is taken at the LAST probe t (scan carries t, not t_min).

    // ---- final Z, block sum (branch keeps pow off the ~4094 zero lanes) ----
    const float P = 1.0f / 4095.0f;
    float lsum = 0.0f;
#pragma unroll
    for (int i = 0; i < VPT; i++) {
        float u = xs[i] - t;
        if (u > 0.0f) {
            lsum += exp2f(P * log2f(u));
        }
    }
#pragma unroll
    for (int off = 16; off > 0; off >>= 1)
        lsum += __shfl_xor_sync(0xFFFFFFFFu, lsum, off);
    if (lane == 0) sh_sum[wid] = lsum;
    __syncthreads();
    float bsum = 0.0f;
#pragma unroll
    for (int w = 0; w < NWARPS; w++) bsum += sh_sum[w];
    const float inv = 1.0f / bsum;

    // ---- write Z/sum (recompute z: ~2 pow calls/row total, saves 16 regs) ----
#pragma unroll
    for (int j = 0; j < 4; j++) {
        float4 v;
#pragma unroll
        for (int k = 0; k < 4; k++) {
            float u = xs[4 * j + k] - t;
            float zi = 0.0f;
            if (u > 0.0f) {
                zi = exp2f(P * log2f(u)) * inv;
            }
            (&v.x)[k] = zi;
        }
        y4[tid + j * NTHREADS] = v;
    }
}

extern "C" void kernel_launch(void* const* d_in, const int* in_sizes, int n_in,
                              void* d_out, int out_size) {
    const float* X = (const float*)d_in[0];
    float* Y = (float*)d_out;
    const int nrows = in_sizes[0] / DIM_D;   // 8*2048 = 16384
    entmax_bisect_kernel<<<nrows, NTHREADS>>>(X, Y);
}

// round 5
// speedup vs baseline: 1.5701x; 1.5701x over previous
#include <cuda_runtime.h>
#include <math.h>

// EntmaxBisect, alpha=1.5, d=4096, 50 bisection iters, p = 1/(d-1) (faithful).
//
// Analytic collapse (validated R1, rel_err 4.6e-8): with p = 1/4095, every
// nonzero Z term u^p lies in [0.975, 1.0001], so the reference fp32 mask
// (sum(Z) - 1 >= 0) is exactly:
//     count(Xs > t) >= 2                         <=>  t < s2
//  || count == 1 && (m - t)^p rounds to >= 1.0f  <=>  fl(m - t) >= U_TH
// The bisection therefore needs only per-row (max, second-max).
//
// R2 changes (ALU-issue bound at 68.5% alu in R1):
//  - bisection runs on thread 0 only, t broadcast via smem (bit-identical
//    trajectory; serial chain hidden by co-resident CTAs)
//  - top-2 on RAW x with branch-free FMNMX; scale by 0.5 only at the end
//    (exact, order-preserving); u = fmaf(0.5,x,-t) == fl(0.5x) - t bitwise
//  - sparsity fast path: a thread touches pow/sum/nonzero-store only if its
//    raw max passes (fmaf(0.5,hi,-t) > 0) -- ~2 threads per CTA
//
// (R5 = R2 resubmitted: three consecutive GPU-broker timeouts; the kernel
//  has not yet run. Unchanged to preserve delta attribution.)

#define NTHREADS 256
#define DIM_D 4096
#define VPT 16
#define NWARPS (NTHREADS / 32)

__global__ __launch_bounds__(NTHREADS)
void entmax_bisect_kernel(const float* __restrict__ X, float* __restrict__ Y) {
    const int tid = threadIdx.x;
    const int lane = tid & 31, wid = tid >> 5;
    const size_t row_off = (size_t)blockIdx.x * DIM_D;
    const float4* __restrict__ x4 = reinterpret_cast<const float4*>(X + row_off);
    float4* __restrict__ y4 = reinterpret_cast<float4*>(Y + row_off);

    __shared__ float sh_hi[NWARPS];
    __shared__ float sh_lo[NWARPS];
    __shared__ float sh_sum[NWARPS];
    __shared__ float sh_t;
    __shared__ float sh_inv;

    // ---- load row (raw; the 0.5 scale folds into later FMAs exactly) ----
    float xs[VPT];
#pragma unroll
    for (int j = 0; j < 4; j++) {
        float4 v = x4[tid + j * NTHREADS];
        xs[4 * j + 0] = v.x;
        xs[4 * j + 1] = v.y;
        xs[4 * j + 2] = v.z;
        xs[4 * j + 3] = v.w;
    }

    // ---- branch-free per-thread top-2 (FMNMX only, no predicates) ----
    float hi = -INFINITY, lo = -INFINITY;
#pragma unroll
    for (int i = 0; i < VPT; i++) {
        float v = xs[i];
        lo = fmaxf(lo, fminf(hi, v));
        hi = fmaxf(hi, v);
    }
    const float thd_hi = hi;  // keep: thread-level sparsity test later

    // ---- warp top-2 (symmetric butterfly combine) ----
#pragma unroll
    for (int off = 16; off > 0; off >>= 1) {
        float h2 = __shfl_xor_sync(0xFFFFFFFFu, hi, off);
        float l2 = __shfl_xor_sync(0xFFFFFFFFu, lo, off);
        if (h2 >= hi) { lo = fmaxf(hi, l2); hi = h2; }
        else          { lo = fmaxf(lo, h2); }
    }
    if (lane == 0) { sh_hi[wid] = hi; sh_lo[wid] = lo; }
    __syncthreads();

    // ---- thread 0: fold warps, scale, run the exact fp32 bisection ----
    if (tid == 0) {
        float mr = -INFINITY, s2r = -INFINITY;
#pragma unroll
        for (int w = 0; w < NWARPS; w++) {
            float h2 = sh_hi[w];
            if (h2 >= mr) { s2r = fmaxf(mr, sh_lo[w]); mr = h2; }
            else          { s2r = fmaxf(s2r, h2); }
        }
        const float m  = 0.5f * mr;   // exact: matches per-element 0.5*x max
        const float s2 = 0.5f * s2r;

        float t_min = m - 1.0f;
        float t_max = m - 0.015625f;  // m - d^(1-alpha) = m - 1/64
        float diff  = t_max - t_min;
        const float U_TH = 0.99987796f;  // (m-t)^(1/4095) rounds to >= 1.0f
        float t = t_min;
#pragma unroll
        for (int it = 0; it < 50; it++) {
            diff = diff * 0.5f;
            t = t_min + diff;
            if ((t < s2) || ((m - t) >= U_TH)) t_min = t;
        }
        sh_t = t;  // Z is taken at the LAST probe t (scan carries t)
    }
    __syncthreads();
    const float t = sh_t;

    // ---- sum(Z): only threads whose max survives do any pow work ----
    const float P = 1.0f / 4095.0f;
    const float thd_u = fmaf(0.5f, thd_hi, -t);  // == fl(0.5*hi) - t bitwise
    float lsum = 0.0f;
    if (thd_u > 0.0f) {
#pragma unroll
        for (int i = 0; i < VPT; i++) {
            float u = fmaf(0.5f, xs[i], -t);
            if (u > 0.0f) lsum += exp2f(P * log2f(u));
        }
    }
#pragma unroll
    for (int off = 16; off > 0; off >>= 1)
        lsum += __shfl_xor_sync(0xFFFFFFFFu, lsum, off);
    if (lane == 0) sh_sum[wid] = lsum;
    __syncthreads();
    if (tid == 0) {
        float bsum = 0.0f;
#pragma unroll
        for (int w = 0; w < NWARPS; w++) bsum += sh_sum[w];
        sh_inv = 1.0f / bsum;
    }
    __syncthreads();
    const float inv = sh_inv;

    // ---- write: zero fast path for the ~254/256 all-zero threads ----
    if (thd_u > 0.0f) {
#pragma unroll
        for (int j = 0; j < 4; j++) {
            float4 v;
#pragma unroll
            for (int k = 0; k < 4; k++) {
                float u = fmaf(0.5f, xs[4 * j + k], -t);
                float zi = 0.0f;
                if (u > 0.0f) zi = exp2f(P * log2f(u)) * inv;
                (&v.x)[k] = zi;
            }
            y4[tid + j * NTHREADS] = v;
        }
    } else {
        const float4 z4 = make_float4(0.0f, 0.0f, 0.0f, 0.0f);
#pragma unroll
        for (int j = 0; j < 4; j++)
            y4[tid + j * NTHREADS] = z4;
    }
}

extern "C" void kernel_launch(void* const* d_in, const int* in_sizes, int n_in,
                              void* d_out, int out_size) {
    const float* X = (const float*)d_in[0];
    float* Y = (float*)d_out;
    const int nrows = in_sizes[0] / DIM_D;   // 8*2048 = 16384
    entmax_bisect_kernel<<<nrows, NTHREADS>>>(X, Y);
}